// round 6
// baseline (speedup 1.0000x reference)
#include <cuda_runtime.h>
#include <cuda_bf16.h>
#include <cstdint>

// Problem constants (fixed by the reference)
#define N_NODES 100000
#define D_FEAT  128
#define E_EDGES 1600000

#define SCAN_CHUNK 256
#define NUM_CHUNKS ((N_NODES + SCAN_CHUNK - 1) / SCAN_CHUNK)   // 391

// Static device scratch (allocation-free rule: __device__ globals)
__device__ float g_h     [(size_t)N_NODES * D_FEAT];  // dis-scaled linear output
__device__ float g_agg   [(size_t)N_NODES * D_FEAT];  // aggregation buffer
__device__ float g_dis   [N_NODES];
__device__ int   g_rowcnt[N_NODES];                   // out-degree histogram (by row)
__device__ int   g_colcnt[N_NODES];                   // in-degree histogram (by col)
__device__ int   g_colptr[N_NODES + 1];               // CSR offsets
__device__ int   g_cursor[N_NODES];                   // fill cursors
__device__ int   g_csrrow[E_EDGES];                   // CSR source (row) indices
__device__ int   g_partial[NUM_CHUNKS];               // scan partials

// ---------------------------------------------------------------------------
// Setup
// ---------------------------------------------------------------------------
__global__ void init_kernel(int* __restrict__ rowcnt, int* __restrict__ colcnt, int n) {
    int i = blockIdx.x * blockDim.x + threadIdx.x;
    if (i < n) { rowcnt[i] = 0; colcnt[i] = 0; }
}

// Histogram both endpoints in one pass over edge_index (int32, [2, E] row-major).
__global__ void hist_kernel(const int* __restrict__ ei,
                            int* __restrict__ rowcnt,
                            int* __restrict__ colcnt, int e) {
    int i = blockIdx.x * blockDim.x + threadIdx.x;
    if (i >= e) return;
    int r = ei[i];
    int c = ei[E_EDGES + i];
    if ((unsigned)r < (unsigned)N_NODES) atomicAdd(&rowcnt[r], 1);
    if ((unsigned)c < (unsigned)N_NODES) atomicAdd(&colcnt[c], 1);
}

__global__ void deg_fin_kernel(const int* __restrict__ rowcnt, float* __restrict__ dis, int n) {
    int i = blockIdx.x * blockDim.x + threadIdx.x;
    if (i < n) dis[i] = rsqrtf((float)(rowcnt[i] + 1));   // +1 = self-loop
}

// ---------------------------------------------------------------------------
// Two-level exclusive scan of colcnt -> colptr (+ cursor copy)
// ---------------------------------------------------------------------------
__global__ void scan_block_sums(const int* __restrict__ colcnt, int* __restrict__ partial, int n) {
    __shared__ int sh[SCAN_CHUNK];
    int b = blockIdx.x, t = threadIdx.x, i = b * SCAN_CHUNK + t;
    sh[t] = (i < n) ? colcnt[i] : 0;
    __syncthreads();
    for (int of = SCAN_CHUNK / 2; of > 0; of >>= 1) {
        if (t < of) sh[t] += sh[t + of];
        __syncthreads();
    }
    if (t == 0) partial[b] = sh[0];
}

__global__ void scan_partials_kernel(int* __restrict__ partial, int* __restrict__ colptr, int nb) {
    __shared__ int sh[512];
    int t = threadIdx.x;
    int v = (t < nb) ? partial[t] : 0;
    sh[t] = v;
    __syncthreads();
    for (int of = 1; of < 512; of <<= 1) {
        int x = (t >= of) ? sh[t - of] : 0;
        __syncthreads();
        sh[t] += x;
        __syncthreads();
    }
    if (t < nb) partial[t] = sh[t] - v;   // exclusive
    if (t == 0) colptr[N_NODES] = E_EDGES;
}

__global__ void scan_chunks_kernel(const int* __restrict__ colcnt,
                                   const int* __restrict__ partial,
                                   int* __restrict__ colptr,
                                   int* __restrict__ cursor, int n) {
    __shared__ int sh[SCAN_CHUNK];
    int b = blockIdx.x, t = threadIdx.x, i = b * SCAN_CHUNK + t;
    int v = (i < n) ? colcnt[i] : 0;
    sh[t] = v;
    __syncthreads();
    for (int of = 1; of < SCAN_CHUNK; of <<= 1) {
        int x = (t >= of) ? sh[t - of] : 0;
        __syncthreads();
        sh[t] += x;
        __syncthreads();
    }
    if (i < n) {
        int excl = sh[t] - v + partial[b];
        colptr[i] = excl;
        cursor[i] = excl;
    }
}

__global__ void csr_fill_kernel(const int* __restrict__ ei,
                                int* __restrict__ cursor,
                                int* __restrict__ csrrow, int e) {
    int i = blockIdx.x * blockDim.x + threadIdx.x;
    if (i >= e) return;
    int r = ei[i];
    int c = ei[E_EDGES + i];
    if ((unsigned)r >= (unsigned)N_NODES || (unsigned)c >= (unsigned)N_NODES) return;
    int pos = atomicAdd(&cursor[c], 1);
    csrrow[pos] = r;
}

// ---------------------------------------------------------------------------
// GEMM: out_h[i] = dis[i] * (act(in[i]) @ W^T + b)
//   PRE==false: act(v) = v                  (layer 1, raw x input)
//   PRE==true : act(v) = relu(dis[i] * v)   (layers 2/3, fused prior epilogue)
// BM=128, BN=128, BK=16, 256 threads, 8x8 microtile, k-major smem tiles,
// double-buffered software pipeline: 1 syncthreads per k-iteration,
// next tile's global loads issued before current tile's compute.
// ---------------------------------------------------------------------------
template <bool PRE>
__global__ __launch_bounds__(256) void gemm_kernel(
    const float* __restrict__ in, const float* __restrict__ W,
    const float* __restrict__ b,  const float* __restrict__ dis,
    float* __restrict__ out_h, int n)
{
    __shared__ float As[2][16 * 128];   // [k][m]  (transposed)
    __shared__ float Ws[2][16 * 128];   // [k][o]  (transposed)

    const int tx = threadIdx.x;
    const int block_row = blockIdx.x * 128;
    const int mrow = tx >> 4;        // 0..15 -> rows mrow*8 .. +7
    const int ncol = tx & 15;        // cols ncol*4..+3 and 64+ncol*4..+3

    // Per-thread load slots: 2 float4 for A, 2 float4 for W per k-tile.
    const int la_r0  = tx >> 2;                  // row for slot 0 (0..63)
    const int la_r1  = (256 + tx) >> 2;          // row for slot 1 (64..127)
    const int la_c4  = (tx & 3) * 4;             // k offset within tile
    const int grow0  = block_row + la_r0;
    const int grow1  = block_row + la_r1;

    float4 va0, va1, vw0, vw1;

    auto load_tiles = [&](int k0) {
        va0 = make_float4(0.f, 0.f, 0.f, 0.f);
        va1 = make_float4(0.f, 0.f, 0.f, 0.f);
        if (grow0 < n) {
            va0 = *(const float4*)(in + (size_t)grow0 * D_FEAT + k0 + la_c4);
            if (PRE) {
                float s = dis[grow0];
                va0.x = fmaxf(va0.x * s, 0.f); va0.y = fmaxf(va0.y * s, 0.f);
                va0.z = fmaxf(va0.z * s, 0.f); va0.w = fmaxf(va0.w * s, 0.f);
            }
        }
        if (grow1 < n) {
            va1 = *(const float4*)(in + (size_t)grow1 * D_FEAT + k0 + la_c4);
            if (PRE) {
                float s = dis[grow1];
                va1.x = fmaxf(va1.x * s, 0.f); va1.y = fmaxf(va1.y * s, 0.f);
                va1.z = fmaxf(va1.z * s, 0.f); va1.w = fmaxf(va1.w * s, 0.f);
            }
        }
        vw0 = *(const float4*)(W + (size_t)la_r0 * D_FEAT + k0 + la_c4);
        vw1 = *(const float4*)(W + (size_t)la_r1 * D_FEAT + k0 + la_c4);
    };

    auto store_tiles = [&](int buf) {
        float* A = As[buf];
        float* Wb = Ws[buf];
        A[(la_c4 + 0) * 128 + la_r0] = va0.x;
        A[(la_c4 + 1) * 128 + la_r0] = va0.y;
        A[(la_c4 + 2) * 128 + la_r0] = va0.z;
        A[(la_c4 + 3) * 128 + la_r0] = va0.w;
        A[(la_c4 + 0) * 128 + la_r1] = va1.x;
        A[(la_c4 + 1) * 128 + la_r1] = va1.y;
        A[(la_c4 + 2) * 128 + la_r1] = va1.z;
        A[(la_c4 + 3) * 128 + la_r1] = va1.w;
        Wb[(la_c4 + 0) * 128 + la_r0] = vw0.x;
        Wb[(la_c4 + 1) * 128 + la_r0] = vw0.y;
        Wb[(la_c4 + 2) * 128 + la_r0] = vw0.z;
        Wb[(la_c4 + 3) * 128 + la_r0] = vw0.w;
        Wb[(la_c4 + 0) * 128 + la_r1] = vw1.x;
        Wb[(la_c4 + 1) * 128 + la_r1] = vw1.y;
        Wb[(la_c4 + 2) * 128 + la_r1] = vw1.z;
        Wb[(la_c4 + 3) * 128 + la_r1] = vw1.w;
    };

    float acc[8][8];
#pragma unroll
    for (int r = 0; r < 8; r++)
#pragma unroll
        for (int c = 0; c < 8; c++) acc[r][c] = 0.0f;

    // Prologue
    load_tiles(0);
    store_tiles(0);
    __syncthreads();

    const int NIT = D_FEAT / 16;   // 8
#pragma unroll
    for (int it = 0; it < NIT; it++) {
        int cur = it & 1;
        if (it + 1 < NIT) load_tiles((it + 1) * 16);

        const float* A = As[cur];
        const float* Wb = Ws[cur];
#pragma unroll
        for (int kk = 0; kk < 16; kk++) {
            float4 a0 = *(const float4*)(A + kk * 128 + mrow * 8);
            float4 a1 = *(const float4*)(A + kk * 128 + mrow * 8 + 4);
            float4 w0 = *(const float4*)(Wb + kk * 128 + ncol * 4);
            float4 w1 = *(const float4*)(Wb + kk * 128 + 64 + ncol * 4);
            float a[8] = {a0.x, a0.y, a0.z, a0.w, a1.x, a1.y, a1.z, a1.w};
            float w[8] = {w0.x, w0.y, w0.z, w0.w, w1.x, w1.y, w1.z, w1.w};
#pragma unroll
            for (int r = 0; r < 8; r++)
#pragma unroll
                for (int c = 0; c < 8; c++) acc[r][c] += a[r] * w[c];
        }

        if (it + 1 < NIT) {
            store_tiles(cur ^ 1);
            __syncthreads();
        }
    }

    // --- epilogue: scale by dis[row], add bias ---
    float4 b0 = *(const float4*)(b + ncol * 4);
    float4 b1 = *(const float4*)(b + 64 + ncol * 4);
#pragma unroll
    for (int r = 0; r < 8; r++) {
        int grow = block_row + mrow * 8 + r;
        if (grow < n) {
            float s = dis[grow];
            float4 v0, v1;
            v0.x = s * (acc[r][0] + b0.x);
            v0.y = s * (acc[r][1] + b0.y);
            v0.z = s * (acc[r][2] + b0.z);
            v0.w = s * (acc[r][3] + b0.w);
            v1.x = s * (acc[r][4] + b1.x);
            v1.y = s * (acc[r][5] + b1.y);
            v1.z = s * (acc[r][6] + b1.z);
            v1.w = s * (acc[r][7] + b1.w);
            size_t off = (size_t)grow * D_FEAT;
            *(float4*)(out_h + off + ncol * 4)      = v0;
            *(float4*)(out_h + off + 64 + ncol * 4) = v1;
        }
    }
}

// ---------------------------------------------------------------------------
// CSR aggregation: warp per destination node. Atomic-free.
//   acc = h[c] (self-loop) + sum_{r in in-neighbors(c)} h[r]
//   final_relu=0: agg[c] = acc      final_relu=1: out[c] = relu(dis[c]*acc)
// ---------------------------------------------------------------------------
__global__ __launch_bounds__(256) void agg_kernel(
    const int* __restrict__ colptr, const int* __restrict__ csrrow,
    const float* __restrict__ h, const float* __restrict__ dis,
    float* __restrict__ outp, int n, int final_relu)
{
    int w    = (blockIdx.x * blockDim.x + threadIdx.x) >> 5;
    int lane = threadIdx.x & 31;
    if (w >= n) return;

    size_t fo = (size_t)lane * 4;
    float4 acc = *(const float4*)(h + (size_t)w * D_FEAT + fo);   // self-loop term

    int beg = __ldg(colptr + w);
    int end = __ldg(colptr + w + 1);
    int i = beg;
    for (; i + 3 < end; i += 4) {
        int r0 = __ldg(csrrow + i);
        int r1 = __ldg(csrrow + i + 1);
        int r2 = __ldg(csrrow + i + 2);
        int r3 = __ldg(csrrow + i + 3);
        float4 v0 = *(const float4*)(h + (size_t)r0 * D_FEAT + fo);
        float4 v1 = *(const float4*)(h + (size_t)r1 * D_FEAT + fo);
        float4 v2 = *(const float4*)(h + (size_t)r2 * D_FEAT + fo);
        float4 v3 = *(const float4*)(h + (size_t)r3 * D_FEAT + fo);
        acc.x += v0.x + v1.x + v2.x + v3.x;
        acc.y += v0.y + v1.y + v2.y + v3.y;
        acc.z += v0.z + v1.z + v2.z + v3.z;
        acc.w += v0.w + v1.w + v2.w + v3.w;
    }
    for (; i < end; i++) {
        int r = __ldg(csrrow + i);
        float4 v = *(const float4*)(h + (size_t)r * D_FEAT + fo);
        acc.x += v.x; acc.y += v.y; acc.z += v.z; acc.w += v.w;
    }

    if (final_relu) {
        float s = dis[w];
        acc.x = fmaxf(s * acc.x, 0.f);
        acc.y = fmaxf(s * acc.y, 0.f);
        acc.z = fmaxf(s * acc.z, 0.f);
        acc.w = fmaxf(s * acc.w, 0.f);
    }
    *(float4*)(outp + (size_t)w * D_FEAT + fo) = acc;
}

// ---------------------------------------------------------------------------
// Launch
// ---------------------------------------------------------------------------
extern "C" void kernel_launch(void* const* d_in, const int* in_sizes, int n_in,
                              void* d_out, int out_size)
{
    const float* x  = (const float*)d_in[0];
    const int*   ei = (const int*)d_in[1];      // JAX x64 disabled -> int32
    const float* W1 = (const float*)d_in[2];
    const float* b1 = (const float*)d_in[3];
    const float* W2 = (const float*)d_in[4];
    const float* b2 = (const float*)d_in[5];
    const float* W3 = (const float*)d_in[6];
    const float* b3 = (const float*)d_in[7];
    float* out = (float*)d_out;

    float *h, *agg, *dis;
    int *rowcnt, *colcnt, *colptr, *cursor, *csrrow, *partial;
    cudaGetSymbolAddress((void**)&h,       g_h);
    cudaGetSymbolAddress((void**)&agg,     g_agg);
    cudaGetSymbolAddress((void**)&dis,     g_dis);
    cudaGetSymbolAddress((void**)&rowcnt,  g_rowcnt);
    cudaGetSymbolAddress((void**)&colcnt,  g_colcnt);
    cudaGetSymbolAddress((void**)&colptr,  g_colptr);
    cudaGetSymbolAddress((void**)&cursor,  g_cursor);
    cudaGetSymbolAddress((void**)&csrrow,  g_csrrow);
    cudaGetSymbolAddress((void**)&partial, g_partial);

    const int n = N_NODES, e = E_EDGES;
    const int gemm_blocks = (n + 127) / 128;
    const int agg_blocks  = (int)(((long long)n * 32 + 255) / 256);

    // Setup part 1: histograms + normalization (gemm1 only needs dis)
    init_kernel<<<(n + 255) / 256, 256>>>(rowcnt, colcnt, n);
    hist_kernel<<<(e + 255) / 256, 256>>>(ei, rowcnt, colcnt, e);
    deg_fin_kernel<<<(n + 255) / 256, 256>>>(rowcnt, dis, n);

    // Layer-1 GEMM (4th launch -> lands in the ncu capture window)
    gemm_kernel<false><<<gemm_blocks, 256>>>(x, W1, b1, dis, h, n);

    // Setup part 2: CSR by destination
    scan_block_sums<<<NUM_CHUNKS, SCAN_CHUNK>>>(colcnt, partial, n);
    scan_partials_kernel<<<1, 512>>>(partial, colptr, NUM_CHUNKS);
    scan_chunks_kernel<<<NUM_CHUNKS, SCAN_CHUNK>>>(colcnt, partial, colptr, cursor, n);
    csr_fill_kernel<<<(e + 255) / 256, 256>>>(ei, cursor, csrrow, e);

    // Layer 1 aggregation
    agg_kernel<<<agg_blocks, 256>>>(colptr, csrrow, h, dis, agg, n, 0);

    // Layer 2
    gemm_kernel<true><<<gemm_blocks, 256>>>(agg, W2, b2, dis, h, n);
    agg_kernel<<<agg_blocks, 256>>>(colptr, csrrow, h, dis, agg, n, 0);

    // Layer 3 (final relu fused into aggregation, writes d_out)
    gemm_kernel<true><<<gemm_blocks, 256>>>(agg, W3, b3, dis, h, n);
    agg_kernel<<<agg_blocks, 256>>>(colptr, csrrow, h, dis, out, n, 1);
}

// round 9
// speedup vs baseline: 1.5943x; 1.5943x over previous
#include <cuda_runtime.h>
#include <cuda_bf16.h>
#include <cstdint>

// Problem constants (fixed by the reference)
#define N_NODES 100000
#define D_FEAT  128
#define E_EDGES 1600000

#define SCAN_CHUNK 256
#define NUM_CHUNKS ((N_NODES + SCAN_CHUNK - 1) / SCAN_CHUNK)   // 391

// Static device scratch (allocation-free rule: __device__ globals)
__device__ float g_h     [(size_t)N_NODES * D_FEAT];  // dis-scaled linear output
__device__ float g_agg   [(size_t)N_NODES * D_FEAT];  // layer output (relu(dis*sum))
__device__ float g_dis   [N_NODES];
__device__ int   g_rowcnt[N_NODES];                   // out-degree histogram (by row)
__device__ int   g_colcnt[N_NODES];                   // in-degree histogram (by col)
__device__ int   g_colptr[N_NODES + 1];               // CSR offsets
__device__ int   g_cursor[N_NODES];                   // fill cursors
__device__ int   g_csrrow[E_EDGES];                   // CSR source (row) indices
__device__ int   g_partial[NUM_CHUNKS];               // scan partials

// ---------------------------------------------------------------------------
// Setup
// ---------------------------------------------------------------------------
__global__ void init_kernel(int* __restrict__ rowcnt, int* __restrict__ colcnt, int n) {
    int i = blockIdx.x * blockDim.x + threadIdx.x;
    if (i < n) { rowcnt[i] = 0; colcnt[i] = 0; }
}

__global__ void hist_kernel(const int* __restrict__ ei,
                            int* __restrict__ rowcnt,
                            int* __restrict__ colcnt, int e) {
    int i = blockIdx.x * blockDim.x + threadIdx.x;
    if (i >= e) return;
    int r = ei[i];
    int c = ei[E_EDGES + i];
    if ((unsigned)r < (unsigned)N_NODES) atomicAdd(&rowcnt[r], 1);
    if ((unsigned)c < (unsigned)N_NODES) atomicAdd(&colcnt[c], 1);
}

__global__ void deg_fin_kernel(const int* __restrict__ rowcnt, float* __restrict__ dis, int n) {
    int i = blockIdx.x * blockDim.x + threadIdx.x;
    if (i < n) dis[i] = rsqrtf((float)(rowcnt[i] + 1));   // +1 = self-loop
}

// ---------------------------------------------------------------------------
// GEMM: out_h[i] = dis[i] * (in[i] @ W^T + b)
// BM=128, BN=128(full), BK=32, 256 threads, 8x8 microtile, k-major smem
// tiles (transposed on store), all inner-loop smem reads = conflict-free
// LDS.128. Static smem only (32KB), no attribute calls.
// ---------------------------------------------------------------------------
__global__ __launch_bounds__(256) void gemm_kernel(
    const float* __restrict__ in, const float* __restrict__ W,
    const float* __restrict__ b,  const float* __restrict__ dis,
    float* __restrict__ out_h, int n)
{
    __shared__ float As[32 * 128];   // [k][m]  (transposed)
    __shared__ float Ws[32 * 128];   // [k][o]  (transposed)

    const int tx = threadIdx.x;
    const int block_row = blockIdx.x * 128;
    const int mrow = tx >> 4;        // 0..15 -> rows mrow*8 .. +7
    const int ncol = tx & 15;        // cols ncol*4..+3 and 64+ncol*4..+3

    float acc[8][8];
#pragma unroll
    for (int r = 0; r < 8; r++)
#pragma unroll
        for (int c = 0; c < 8; c++) acc[r][c] = 0.0f;

    for (int k0 = 0; k0 < D_FEAT; k0 += 32) {
        // --- A tile: 128 rows x 32 k = 1024 float4, 4 per thread, transposed ---
#pragma unroll
        for (int it = 0; it < 4; it++) {
            int idx = it * 256 + tx;             // 0..1023
            int r   = idx >> 3;                  // 8 float4 per row
            int c4  = (idx & 7) * 4;
            int grow = block_row + r;
            float4 v = make_float4(0.f, 0.f, 0.f, 0.f);
            if (grow < n)
                v = *(const float4*)(in + (size_t)grow * D_FEAT + k0 + c4);
            As[(c4 + 0) * 128 + r] = v.x;
            As[(c4 + 1) * 128 + r] = v.y;
            As[(c4 + 2) * 128 + r] = v.z;
            As[(c4 + 3) * 128 + r] = v.w;
        }
        // --- W tile: 128 o x 32 k = 1024 float4, transposed ---
#pragma unroll
        for (int it = 0; it < 4; it++) {
            int idx = it * 256 + tx;
            int o   = idx >> 3;
            int kq  = (idx & 7) * 4;
            float4 v = *(const float4*)(W + (size_t)o * D_FEAT + k0 + kq);
            Ws[(kq + 0) * 128 + o] = v.x;
            Ws[(kq + 1) * 128 + o] = v.y;
            Ws[(kq + 2) * 128 + o] = v.z;
            Ws[(kq + 3) * 128 + o] = v.w;
        }
        __syncthreads();

#pragma unroll
        for (int kk = 0; kk < 32; kk++) {
            float4 a0 = *(const float4*)(As + kk * 128 + mrow * 8);
            float4 a1 = *(const float4*)(As + kk * 128 + mrow * 8 + 4);
            float4 w0 = *(const float4*)(Ws + kk * 128 + ncol * 4);
            float4 w1 = *(const float4*)(Ws + kk * 128 + 64 + ncol * 4);
            float a[8] = {a0.x, a0.y, a0.z, a0.w, a1.x, a1.y, a1.z, a1.w};
            float w[8] = {w0.x, w0.y, w0.z, w0.w, w1.x, w1.y, w1.z, w1.w};
#pragma unroll
            for (int r = 0; r < 8; r++)
#pragma unroll
                for (int c = 0; c < 8; c++) acc[r][c] += a[r] * w[c];
        }
        __syncthreads();
    }

    // ---- epilogue: scale by dis[row], add bias ----
    float4 b0 = *(const float4*)(b + ncol * 4);
    float4 b1 = *(const float4*)(b + 64 + ncol * 4);
#pragma unroll
    for (int r = 0; r < 8; r++) {
        int grow = block_row + mrow * 8 + r;
        if (grow < n) {
            float s = dis[grow];
            float4 v0, v1;
            v0.x = s * (acc[r][0] + b0.x);
            v0.y = s * (acc[r][1] + b0.y);
            v0.z = s * (acc[r][2] + b0.z);
            v0.w = s * (acc[r][3] + b0.w);
            v1.x = s * (acc[r][4] + b1.x);
            v1.y = s * (acc[r][5] + b1.y);
            v1.z = s * (acc[r][6] + b1.z);
            v1.w = s * (acc[r][7] + b1.w);
            size_t off = (size_t)grow * D_FEAT;
            *(float4*)(out_h + off + ncol * 4)      = v0;
            *(float4*)(out_h + off + 64 + ncol * 4) = v1;
        }
    }
}

// ---------------------------------------------------------------------------
// Two-level exclusive scan of colcnt -> colptr (+ cursor copy)
// ---------------------------------------------------------------------------
__global__ void scan_block_sums(const int* __restrict__ colcnt, int* __restrict__ partial, int n) {
    __shared__ int sh[SCAN_CHUNK];
    int b = blockIdx.x, t = threadIdx.x, i = b * SCAN_CHUNK + t;
    sh[t] = (i < n) ? colcnt[i] : 0;
    __syncthreads();
    for (int of = SCAN_CHUNK / 2; of > 0; of >>= 1) {
        if (t < of) sh[t] += sh[t + of];
        __syncthreads();
    }
    if (t == 0) partial[b] = sh[0];
}

__global__ void scan_partials_kernel(int* __restrict__ partial, int* __restrict__ colptr, int nb) {
    __shared__ int sh[512];
    int t = threadIdx.x;
    int v = (t < nb) ? partial[t] : 0;
    sh[t] = v;
    __syncthreads();
    for (int of = 1; of < 512; of <<= 1) {
        int x = (t >= of) ? sh[t - of] : 0;
        __syncthreads();
        sh[t] += x;
        __syncthreads();
    }
    if (t < nb) partial[t] = sh[t] - v;   // exclusive
    if (t == 0) colptr[N_NODES] = E_EDGES;
}

__global__ void scan_chunks_kernel(const int* __restrict__ colcnt,
                                   const int* __restrict__ partial,
                                   int* __restrict__ colptr,
                                   int* __restrict__ cursor, int n) {
    __shared__ int sh[SCAN_CHUNK];
    int b = blockIdx.x, t = threadIdx.x, i = b * SCAN_CHUNK + t;
    int v = (i < n) ? colcnt[i] : 0;
    sh[t] = v;
    __syncthreads();
    for (int of = 1; of < SCAN_CHUNK; of <<= 1) {
        int x = (t >= of) ? sh[t - of] : 0;
        __syncthreads();
        sh[t] += x;
        __syncthreads();
    }
    if (i < n) {
        int excl = sh[t] - v + partial[b];
        colptr[i] = excl;
        cursor[i] = excl;
    }
}

__global__ void csr_fill_kernel(const int* __restrict__ ei,
                                int* __restrict__ cursor,
                                int* __restrict__ csrrow, int e) {
    int i = blockIdx.x * blockDim.x + threadIdx.x;
    if (i >= e) return;
    int r = ei[i];
    int c = ei[E_EDGES + i];
    if ((unsigned)r >= (unsigned)N_NODES || (unsigned)c >= (unsigned)N_NODES) return;
    int pos = atomicAdd(&cursor[c], 1);
    csrrow[pos] = r;
}

// ---------------------------------------------------------------------------
// CSR aggregation: warp per destination node. Atomic-free.
//   out[c] = relu(dis[c] * (h[c] + sum_{r in in-neighbors(c)} h[r]))
// This IS the layer output (and the next layer's GEMM input).
// ---------------------------------------------------------------------------
__global__ __launch_bounds__(256) void agg_kernel(
    const int* __restrict__ colptr, const int* __restrict__ csrrow,
    const float* __restrict__ h, const float* __restrict__ dis,
    float* __restrict__ outp, int n)
{
    int w    = (blockIdx.x * blockDim.x + threadIdx.x) >> 5;
    int lane = threadIdx.x & 31;
    if (w >= n) return;

    size_t fo = (size_t)lane * 4;
    float4 acc = *(const float4*)(h + (size_t)w * D_FEAT + fo);   // self-loop term

    int beg = __ldg(colptr + w);
    int end = __ldg(colptr + w + 1);
    int i = beg;
    for (; i + 3 < end; i += 4) {
        int r0 = __ldg(csrrow + i);
        int r1 = __ldg(csrrow + i + 1);
        int r2 = __ldg(csrrow + i + 2);
        int r3 = __ldg(csrrow + i + 3);
        float4 v0 = *(const float4*)(h + (size_t)r0 * D_FEAT + fo);
        float4 v1 = *(const float4*)(h + (size_t)r1 * D_FEAT + fo);
        float4 v2 = *(const float4*)(h + (size_t)r2 * D_FEAT + fo);
        float4 v3 = *(const float4*)(h + (size_t)r3 * D_FEAT + fo);
        acc.x += v0.x + v1.x + v2.x + v3.x;
        acc.y += v0.y + v1.y + v2.y + v3.y;
        acc.z += v0.z + v1.z + v2.z + v3.z;
        acc.w += v0.w + v1.w + v2.w + v3.w;
    }
    for (; i < end; i++) {
        int r = __ldg(csrrow + i);
        float4 v = *(const float4*)(h + (size_t)r * D_FEAT + fo);
        acc.x += v.x; acc.y += v.y; acc.z += v.z; acc.w += v.w;
    }

    float s = dis[w];
    acc.x = fmaxf(s * acc.x, 0.f);
    acc.y = fmaxf(s * acc.y, 0.f);
    acc.z = fmaxf(s * acc.z, 0.f);
    acc.w = fmaxf(s * acc.w, 0.f);
    *(float4*)(outp + (size_t)w * D_FEAT + fo) = acc;
}

// ---------------------------------------------------------------------------
// Launch
// ---------------------------------------------------------------------------
extern "C" void kernel_launch(void* const* d_in, const int* in_sizes, int n_in,
                              void* d_out, int out_size)
{
    const float* x  = (const float*)d_in[0];
    const int*   ei = (const int*)d_in[1];      // JAX x64 disabled -> int32
    const float* W1 = (const float*)d_in[2];
    const float* b1 = (const float*)d_in[3];
    const float* W2 = (const float*)d_in[4];
    const float* b2 = (const float*)d_in[5];
    const float* W3 = (const float*)d_in[6];
    const float* b3 = (const float*)d_in[7];
    float* out = (float*)d_out;

    float *h, *agg, *dis;
    int *rowcnt, *colcnt, *colptr, *cursor, *csrrow, *partial;
    cudaGetSymbolAddress((void**)&h,       g_h);
    cudaGetSymbolAddress((void**)&agg,     g_agg);
    cudaGetSymbolAddress((void**)&dis,     g_dis);
    cudaGetSymbolAddress((void**)&rowcnt,  g_rowcnt);
    cudaGetSymbolAddress((void**)&colcnt,  g_colcnt);
    cudaGetSymbolAddress((void**)&colptr,  g_colptr);
    cudaGetSymbolAddress((void**)&cursor,  g_cursor);
    cudaGetSymbolAddress((void**)&csrrow,  g_csrrow);
    cudaGetSymbolAddress((void**)&partial, g_partial);

    const int n = N_NODES, e = E_EDGES;
    const int gemm_blocks = (n + 127) / 128;
    const int agg_blocks  = (int)(((long long)n * 32 + 255) / 256);

    // Setup part 1: histograms + normalization (gemm1 only needs dis)
    init_kernel<<<(n + 255) / 256, 256>>>(rowcnt, colcnt, n);
    hist_kernel<<<(e + 255) / 256, 256>>>(ei, rowcnt, colcnt, e);
    deg_fin_kernel<<<(n + 255) / 256, 256>>>(rowcnt, dis, n);

    // Layer-1 GEMM (4th launch -> lands in the ncu capture window)
    gemm_kernel<<<gemm_blocks, 256>>>(x, W1, b1, dis, h, n);

    // Setup part 2: CSR by destination
    scan_block_sums<<<NUM_CHUNKS, SCAN_CHUNK>>>(colcnt, partial, n);
    scan_partials_kernel<<<1, 512>>>(partial, colptr, NUM_CHUNKS);
    scan_chunks_kernel<<<NUM_CHUNKS, SCAN_CHUNK>>>(colcnt, partial, colptr, cursor, n);
    csr_fill_kernel<<<(e + 255) / 256, 256>>>(ei, cursor, csrrow, e);

    // Layer 1 aggregation (output = relu(dis*sum) = layer-2 input)
    agg_kernel<<<agg_blocks, 256>>>(colptr, csrrow, h, dis, agg, n);

    // Layer 2
    gemm_kernel<<<gemm_blocks, 256>>>(agg, W2, b2, dis, h, n);
    agg_kernel<<<agg_blocks, 256>>>(colptr, csrrow, h, dis, agg, n);

    // Layer 3 (writes d_out directly)
    gemm_kernel<<<gemm_blocks, 256>>>(agg, W3, b3, dis, h, n);
    agg_kernel<<<agg_blocks, 256>>>(colptr, csrrow, h, dis, out, n);
}

// round 11
// speedup vs baseline: 2.3115x; 1.4499x over previous
#include <cuda_runtime.h>
#include <cuda_bf16.h>
#include <cstdint>

// Problem constants (fixed by the reference)
#define N_NODES 100000
#define D_FEAT  128
#define E_EDGES 1600000

#define SCAN_CHUNK 256
#define NUM_CHUNKS ((N_NODES + SCAN_CHUNK - 1) / SCAN_CHUNK)   // 391

// GEMM smem: 4 arrays of [128][68] u32 (AH, AL, WH, WL)
#define ASTRIDE 68
#define GEMM_DSMEM (4 * 128 * ASTRIDE * 4)   // 139264 bytes

// Static device scratch (allocation-free rule: __device__ globals)
__device__ float g_h     [(size_t)N_NODES * D_FEAT];  // dis-scaled linear output
__device__ float g_agg   [(size_t)N_NODES * D_FEAT];  // layer output (relu(dis*sum))
__device__ float g_dis   [N_NODES];
__device__ int   g_rowcnt[N_NODES];
__device__ int   g_colcnt[N_NODES];
__device__ int   g_colptr[N_NODES + 1];
__device__ int   g_cursor[N_NODES];
__device__ int   g_csrrow[E_EDGES];
__device__ int   g_partial[NUM_CHUNKS];

// ---------------------------------------------------------------------------
// Setup kernels (unchanged, passing since round 9)
// ---------------------------------------------------------------------------
__global__ void init_kernel(int* __restrict__ rowcnt, int* __restrict__ colcnt, int n) {
    int i = blockIdx.x * blockDim.x + threadIdx.x;
    if (i < n) { rowcnt[i] = 0; colcnt[i] = 0; }
}

__global__ void hist_kernel(const int* __restrict__ ei,
                            int* __restrict__ rowcnt,
                            int* __restrict__ colcnt, int e) {
    int i = blockIdx.x * blockDim.x + threadIdx.x;
    if (i >= e) return;
    int r = ei[i];
    int c = ei[E_EDGES + i];
    if ((unsigned)r < (unsigned)N_NODES) atomicAdd(&rowcnt[r], 1);
    if ((unsigned)c < (unsigned)N_NODES) atomicAdd(&colcnt[c], 1);
}

__global__ void deg_fin_kernel(const int* __restrict__ rowcnt, float* __restrict__ dis, int n) {
    int i = blockIdx.x * blockDim.x + threadIdx.x;
    if (i < n) dis[i] = rsqrtf((float)(rowcnt[i] + 1));
}

// ---------------------------------------------------------------------------
// bf16 hi/lo split of a float4 into two packed-pair words each
// word layout: low 16 bits = even-k element, high 16 bits = odd-k element
// ---------------------------------------------------------------------------
__device__ __forceinline__ void cvt_hilo(float4 v, uint2& h, uint2& l) {
    __nv_bfloat162 h0 = __float22bfloat162_rn(make_float2(v.x, v.y));
    __nv_bfloat162 h1 = __float22bfloat162_rn(make_float2(v.z, v.w));
    float2 f0 = __bfloat1622float2(h0);
    float2 f1 = __bfloat1622float2(h1);
    __nv_bfloat162 l0 = __float22bfloat162_rn(make_float2(v.x - f0.x, v.y - f0.y));
    __nv_bfloat162 l1 = __float22bfloat162_rn(make_float2(v.z - f1.x, v.w - f1.y));
    h.x = *(uint32_t*)&h0; h.y = *(uint32_t*)&h1;
    l.x = *(uint32_t*)&l0; l.y = *(uint32_t*)&l1;
}

#define MMA_BF16(d, a, b0, b1) \
    asm volatile("mma.sync.aligned.m16n8k16.row.col.f32.bf16.bf16.f32 " \
        "{%0,%1,%2,%3}, {%4,%5,%6,%7}, {%8,%9}, {%0,%1,%2,%3};" \
        : "+f"((d)[0]), "+f"((d)[1]), "+f"((d)[2]), "+f"((d)[3]) \
        : "r"((a)[0]), "r"((a)[1]), "r"((a)[2]), "r"((a)[3]), "r"(b0), "r"(b1))

// ---------------------------------------------------------------------------
// Tensor-core GEMM (legacy mma.sync path, compute_100-safe):
//   out_h[m] = dis[m] * (in[m] @ W^T + b)
// BM=128/CTA, 512 threads = 16 warps in 4(m) x 4(n); warp tile 32x32
// (2 m-tiles x 4 n-tiles of m16n8k16). K=128 = 8 k-steps.
// A and W pre-split into bf16 hi/lo packed pairs in smem; 3-product
// Dekker accumulation in fp32. All fragment LDS are conflict-free
// (bank = (lane + const) & 31 by construction with stride 68).
// ---------------------------------------------------------------------------
__global__ __launch_bounds__(512) void gemm_mma_kernel(
    const float* __restrict__ in, const float* __restrict__ Wm,
    const float* __restrict__ bias, const float* __restrict__ dis,
    float* __restrict__ out_h, int n)
{
    extern __shared__ uint32_t sm[];
    uint32_t* AH = sm;
    uint32_t* AL = sm + 128 * ASTRIDE;
    uint32_t* WH = sm + 2 * 128 * ASTRIDE;
    uint32_t* WL = sm + 3 * 128 * ASTRIDE;

    const int tx = threadIdx.x;
    const int wid = tx >> 5;
    const int lane = tx & 31;
    const int block_row = blockIdx.x * 128;

    // ---- fill: 4096 float4 each for A and W; convert + pack + store ----
#pragma unroll
    for (int it = 0; it < 8; it++) {
        int idx = it * 512 + tx;          // 0..4095
        int row = idx >> 5;               // 32 float4 per 128-float row
        int c4  = (idx & 31) * 4;         // k offset
        int p   = row * ASTRIDE + (c4 >> 1);

        int grow = block_row + row;
        float4 va = make_float4(0.f, 0.f, 0.f, 0.f);
        if (grow < n) va = *(const float4*)(in + (size_t)grow * D_FEAT + c4);
        uint2 ah, al; cvt_hilo(va, ah, al);
        *(uint2*)(AH + p) = ah;
        *(uint2*)(AL + p) = al;

        float4 vw = *(const float4*)(Wm + (size_t)row * D_FEAT + c4);
        uint2 wh, wl; cvt_hilo(vw, wh, wl);
        *(uint2*)(WH + p) = wh;
        *(uint2*)(WL + p) = wl;
    }
    __syncthreads();

    const int wm = wid & 3;               // m-warp 0..3  (32 rows each)
    const int wn = wid >> 2;              // n-warp 0..3  (32 cols each)
    const int g  = lane >> 2;             // groupID
    const int t4 = lane & 3;              // threadID-in-group

    float acc[2][4][4];
#pragma unroll
    for (int mt = 0; mt < 2; mt++)
#pragma unroll
        for (int nt = 0; nt < 4; nt++)
#pragma unroll
            for (int j = 0; j < 4; j++) acc[mt][nt][j] = 0.f;

#pragma unroll
    for (int ks = 0; ks < 8; ks++) {
        int kp = ks * 8;                  // kpair base
        uint32_t ah[2][4], al[2][4];
#pragma unroll
        for (int mt = 0; mt < 2; mt++) {
            int r0 = (wm * 32 + mt * 16 + g) * ASTRIDE + kp + t4;
            int r1 = r0 + 8 * ASTRIDE;
            ah[mt][0] = AH[r0];     ah[mt][1] = AH[r1];
            ah[mt][2] = AH[r0 + 4]; ah[mt][3] = AH[r1 + 4];
            al[mt][0] = AL[r0];     al[mt][1] = AL[r1];
            al[mt][2] = AL[r0 + 4]; al[mt][3] = AL[r1 + 4];
        }
#pragma unroll
        for (int nt = 0; nt < 4; nt++) {
            int c0 = (wn * 32 + nt * 8 + g) * ASTRIDE + kp + t4;
            uint32_t bh0 = WH[c0], bh1 = WH[c0 + 4];
            uint32_t bl0 = WL[c0], bl1 = WL[c0 + 4];
#pragma unroll
            for (int mt = 0; mt < 2; mt++) {
                MMA_BF16(acc[mt][nt], ah[mt], bh0, bh1);   // hi*hi
                MMA_BF16(acc[mt][nt], ah[mt], bl0, bl1);   // hi*lo
                MMA_BF16(acc[mt][nt], al[mt], bh0, bh1);   // lo*hi
            }
        }
    }

    // ---- epilogue: d0,d1 -> (row, 2t4/2t4+1); d2,d3 -> row+8 ----
#pragma unroll
    for (int mt = 0; mt < 2; mt++) {
        int row0 = block_row + wm * 32 + mt * 16 + g;
        int row1 = row0 + 8;
        float s0 = (row0 < n) ? dis[row0] : 0.f;
        float s1 = (row1 < n) ? dis[row1] : 0.f;
#pragma unroll
        for (int nt = 0; nt < 4; nt++) {
            int col = wn * 32 + nt * 8 + 2 * t4;
            float2 b2 = *(const float2*)(bias + col);
            if (row0 < n) {
                float2 o;
                o.x = s0 * (acc[mt][nt][0] + b2.x);
                o.y = s0 * (acc[mt][nt][1] + b2.y);
                *(float2*)(out_h + (size_t)row0 * D_FEAT + col) = o;
            }
            if (row1 < n) {
                float2 o;
                o.x = s1 * (acc[mt][nt][2] + b2.x);
                o.y = s1 * (acc[mt][nt][3] + b2.y);
                *(float2*)(out_h + (size_t)row1 * D_FEAT + col) = o;
            }
        }
    }
}

// ---------------------------------------------------------------------------
// Scan / CSR (unchanged from round 9)
// ---------------------------------------------------------------------------
__global__ void scan_block_sums(const int* __restrict__ colcnt, int* __restrict__ partial, int n) {
    __shared__ int sh[SCAN_CHUNK];
    int b = blockIdx.x, t = threadIdx.x, i = b * SCAN_CHUNK + t;
    sh[t] = (i < n) ? colcnt[i] : 0;
    __syncthreads();
    for (int of = SCAN_CHUNK / 2; of > 0; of >>= 1) {
        if (t < of) sh[t] += sh[t + of];
        __syncthreads();
    }
    if (t == 0) partial[b] = sh[0];
}

__global__ void scan_partials_kernel(int* __restrict__ partial, int* __restrict__ colptr, int nb) {
    __shared__ int sh[512];
    int t = threadIdx.x;
    int v = (t < nb) ? partial[t] : 0;
    sh[t] = v;
    __syncthreads();
    for (int of = 1; of < 512; of <<= 1) {
        int x = (t >= of) ? sh[t - of] : 0;
        __syncthreads();
        sh[t] += x;
        __syncthreads();
    }
    if (t < nb) partial[t] = sh[t] - v;
    if (t == 0) colptr[N_NODES] = E_EDGES;
}

__global__ void scan_chunks_kernel(const int* __restrict__ colcnt,
                                   const int* __restrict__ partial,
                                   int* __restrict__ colptr,
                                   int* __restrict__ cursor, int n) {
    __shared__ int sh[SCAN_CHUNK];
    int b = blockIdx.x, t = threadIdx.x, i = b * SCAN_CHUNK + t;
    int v = (i < n) ? colcnt[i] : 0;
    sh[t] = v;
    __syncthreads();
    for (int of = 1; of < SCAN_CHUNK; of <<= 1) {
        int x = (t >= of) ? sh[t - of] : 0;
        __syncthreads();
        sh[t] += x;
        __syncthreads();
    }
    if (i < n) {
        int excl = sh[t] - v + partial[b];
        colptr[i] = excl;
        cursor[i] = excl;
    }
}

__global__ void csr_fill_kernel(const int* __restrict__ ei,
                                int* __restrict__ cursor,
                                int* __restrict__ csrrow, int e) {
    int i = blockIdx.x * blockDim.x + threadIdx.x;
    if (i >= e) return;
    int r = ei[i];
    int c = ei[E_EDGES + i];
    if ((unsigned)r >= (unsigned)N_NODES || (unsigned)c >= (unsigned)N_NODES) return;
    int pos = atomicAdd(&cursor[c], 1);
    csrrow[pos] = r;
}

// ---------------------------------------------------------------------------
// CSR aggregation (unchanged from round 9)
//   out[c] = relu(dis[c] * (h[c] + sum_{r in in-neighbors(c)} h[r]))
// ---------------------------------------------------------------------------
__global__ __launch_bounds__(256) void agg_kernel(
    const int* __restrict__ colptr, const int* __restrict__ csrrow,
    const float* __restrict__ h, const float* __restrict__ dis,
    float* __restrict__ outp, int n)
{
    int w    = (blockIdx.x * blockDim.x + threadIdx.x) >> 5;
    int lane = threadIdx.x & 31;
    if (w >= n) return;

    size_t fo = (size_t)lane * 4;
    float4 acc = *(const float4*)(h + (size_t)w * D_FEAT + fo);

    int beg = __ldg(colptr + w);
    int end = __ldg(colptr + w + 1);
    int i = beg;
    for (; i + 3 < end; i += 4) {
        int r0 = __ldg(csrrow + i);
        int r1 = __ldg(csrrow + i + 1);
        int r2 = __ldg(csrrow + i + 2);
        int r3 = __ldg(csrrow + i + 3);
        float4 v0 = *(const float4*)(h + (size_t)r0 * D_FEAT + fo);
        float4 v1 = *(const float4*)(h + (size_t)r1 * D_FEAT + fo);
        float4 v2 = *(const float4*)(h + (size_t)r2 * D_FEAT + fo);
        float4 v3 = *(const float4*)(h + (size_t)r3 * D_FEAT + fo);
        acc.x += v0.x + v1.x + v2.x + v3.x;
        acc.y += v0.y + v1.y + v2.y + v3.y;
        acc.z += v0.z + v1.z + v2.z + v3.z;
        acc.w += v0.w + v1.w + v2.w + v3.w;
    }
    for (; i < end; i++) {
        int r = __ldg(csrrow + i);
        float4 v = *(const float4*)(h + (size_t)r * D_FEAT + fo);
        acc.x += v.x; acc.y += v.y; acc.z += v.z; acc.w += v.w;
    }

    float s = dis[w];
    acc.x = fmaxf(s * acc.x, 0.f);
    acc.y = fmaxf(s * acc.y, 0.f);
    acc.z = fmaxf(s * acc.z, 0.f);
    acc.w = fmaxf(s * acc.w, 0.f);
    *(float4*)(outp + (size_t)w * D_FEAT + fo) = acc;
}

// ---------------------------------------------------------------------------
// Launch
// ---------------------------------------------------------------------------
extern "C" void kernel_launch(void* const* d_in, const int* in_sizes, int n_in,
                              void* d_out, int out_size)
{
    const float* x  = (const float*)d_in[0];
    const int*   ei = (const int*)d_in[1];      // JAX x64 disabled -> int32
    const float* W1 = (const float*)d_in[2];
    const float* b1 = (const float*)d_in[3];
    const float* W2 = (const float*)d_in[4];
    const float* b2 = (const float*)d_in[5];
    const float* W3 = (const float*)d_in[6];
    const float* b3 = (const float*)d_in[7];
    float* out = (float*)d_out;

    float *h, *agg, *dis;
    int *rowcnt, *colcnt, *colptr, *cursor, *csrrow, *partial;
    cudaGetSymbolAddress((void**)&h,       g_h);
    cudaGetSymbolAddress((void**)&agg,     g_agg);
    cudaGetSymbolAddress((void**)&dis,     g_dis);
    cudaGetSymbolAddress((void**)&rowcnt,  g_rowcnt);
    cudaGetSymbolAddress((void**)&colcnt,  g_colcnt);
    cudaGetSymbolAddress((void**)&colptr,  g_colptr);
    cudaGetSymbolAddress((void**)&cursor,  g_cursor);
    cudaGetSymbolAddress((void**)&csrrow,  g_csrrow);
    cudaGetSymbolAddress((void**)&partial, g_partial);

    // Unconditional each call (no static guards). Host-side, capture-safe.
    cudaFuncSetAttribute(gemm_mma_kernel, cudaFuncAttributeMaxDynamicSharedMemorySize,
                         GEMM_DSMEM);

    const int n = N_NODES, e = E_EDGES;
    const int gemm_blocks = (n + 127) / 128;   // 782
    const int agg_blocks  = (int)(((long long)n * 32 + 255) / 256);

    // Setup part 1: histograms + normalization
    init_kernel<<<(n + 255) / 256, 256>>>(rowcnt, colcnt, n);
    hist_kernel<<<(e + 255) / 256, 256>>>(ei, rowcnt, colcnt, e);
    deg_fin_kernel<<<(n + 255) / 256, 256>>>(rowcnt, dis, n);

    // Layer-1 GEMM (4th launch -> ncu capture window)
    gemm_mma_kernel<<<gemm_blocks, 512, GEMM_DSMEM>>>(x, W1, b1, dis, h, n);

    // Setup part 2: CSR by destination
    scan_block_sums<<<NUM_CHUNKS, SCAN_CHUNK>>>(colcnt, partial, n);
    scan_partials_kernel<<<1, 512>>>(partial, colptr, NUM_CHUNKS);
    scan_chunks_kernel<<<NUM_CHUNKS, SCAN_CHUNK>>>(colcnt, partial, colptr, cursor, n);
    csr_fill_kernel<<<(e + 255) / 256, 256>>>(ei, cursor, csrrow, e);

    // Layer 1 aggregation (relu(dis*sum) = layer-2 input)
    agg_kernel<<<agg_blocks, 256>>>(colptr, csrrow, h, dis, agg, n);

    // Layer 2
    gemm_mma_kernel<<<gemm_blocks, 512, GEMM_DSMEM>>>(agg, W2, b2, dis, h, n);
    agg_kernel<<<agg_blocks, 256>>>(colptr, csrrow, h, dis, agg, n);

    // Layer 3 (writes d_out)
    gemm_mma_kernel<<<gemm_blocks, 512, GEMM_DSMEM>>>(agg, W3, b3, dis, h, n);
    agg_kernel<<<agg_blocks, 256>>>(colptr, csrrow, h, dis, out, n);
}